// round 12
// baseline (speedup 1.0000x reference)
#include <cuda_runtime.h>
#include <cuda_bf16.h>
#include <cstdint>

#define NDRUG 846
#define EDIM  64
#define SNEI  1024
#define RLEN  100
#define NPAIR (NDRUG / 2)    // 423
#define XCTAS ((NDRUG + 3) / 4)   // 212

// ---- scratch (__device__ globals: no allocation allowed) ----
__device__ float g_b2s[SNEI];
__device__ float g_we[NDRUG * EDIM];
__device__ float g_x[NDRUG * EDIM];
__device__ float g_sum[EDIM];
__device__ float g_sq[EDIM];
__device__ int   g_xdone;            // zero-init; self-resetting

__device__ __forceinline__ unsigned pack_bf2(float a, float b) {
    __nv_bfloat16 ha = __float2bfloat16(a), hb = __float2bfloat16(b);
    return (unsigned)__bfloat16_as_ushort(ha) | ((unsigned)__bfloat16_as_ushort(hb) << 16);
}
__device__ __forceinline__ void split2(float x, float& hi, float& lo) {
    __nv_bfloat16 h = __float2bfloat16(x);
    hi = __bfloat162float(h);
    lo = x - hi;
}
__device__ __forceinline__ void mma16816(float* d, const unsigned* a, const unsigned* b) {
    asm volatile(
        "mma.sync.aligned.m16n8k16.row.col.f32.bf16.bf16.f32 "
        "{%0,%1,%2,%3}, {%4,%5,%6,%7}, {%8,%9}, {%0,%1,%2,%3};"
        : "+f"(d[0]), "+f"(d[1]), "+f"(d[2]), "+f"(d[3])
        : "r"(a[0]), "r"(a[1]), "r"(a[2]), "r"(a[3]), "r"(b[0]), "r"(b[1]));
}

// ------------------------------------------------------------------
// kernel 0: b2sum + zero BN accumulators
// ------------------------------------------------------------------
__global__ void k_b2sum(const float* __restrict__ b2) {
    int wid = threadIdx.x >> 5, lane = threadIdx.x & 31;
    if (blockIdx.x == 0 && threadIdx.x < 2 * EDIM) {
        if (threadIdx.x < EDIM) g_sum[threadIdx.x] = 0.f;
        else                    g_sq[threadIdx.x - EDIM] = 0.f;
    }
    int s = blockIdx.x * 8 + wid;
    if (s >= SNEI) return;
    float2 v = *reinterpret_cast<const float2*>(b2 + s * 64 + lane * 2);
    float acc = v.x + v.y;
    #pragma unroll
    for (int o = 16; o; o >>= 1) acc += __shfl_xor_sync(0xffffffffu, acc, o);
    if (lane == 0) g_b2s[s] = acc;
}

// ------------------------------------------------------------------
// kernel 1: one CTA per drug pair. Fused W1 prep, mma.sync GEMM,
//   paired score loop, half-CTA-per-drug softmax + compacted gather.
//
// smem u32 (staging epoch): A_hi[0,4032) A_lo[4032,8064)
//   B0h[8064,10368) B0l[10368,12672) B1h[12672,14976) B1l[14976,17280)
// float overlay (post-GEMM): Ms0@0 Ms1@6800 scores0@13600 scores1@14624
//   cidx0@15648 cidx1@16672 psum2a@17696 psum2b@17952 red@18208
//   cnt0@18240 cnt1@18241
// non-overlay: w2s0@18244 w2s1@18308 psum0@18372..18628
#define K1_SMEM_FLOATS 18628
#define K1_SMEM_BYTES  (K1_SMEM_FLOATS * 4)
#define A_HI 0
#define A_LO 4032
#define B0H  8064
#define B0L  10368
#define B1H  12672
#define B1L  14976

__global__ void __launch_bounds__(256, 3)
k_drug(const int*   __restrict__ dn,
       const int*   __restrict__ adjt,
       const int*   __restrict__ adjr,
       const float* __restrict__ drug_table,
       const float* __restrict__ rela_table,
       const float* __restrict__ ent_table,
       const float* __restrict__ W1,
       const float* __restrict__ b1,
       const float* __restrict__ W2) {
    extern __shared__ float sm[];
    unsigned* smu = reinterpret_cast<unsigned*>(sm);
    // overlay views
    float* Ms0     = sm;
    float* Ms1     = sm + 6800;
    float* scores0 = sm + 13600;
    float* scores1 = sm + 14624;
    int*   cidx0   = (int*)(sm + 15648);
    int*   cidx1   = (int*)(sm + 16672);
    float* psum2a  = sm + 17696;
    float* psum2b  = sm + 17952;
    float* red     = sm + 18208;
    int*   cnt0    = (int*)(sm + 18240);
    int*   cnt1    = (int*)(sm + 18241);
    // non-overlay
    float* w2s0  = sm + 18244;
    float* w2s1  = sm + 18308;
    float* psum0 = sm + 18372;

    const int n0   = blockIdx.x * 2;
    const int tid  = threadIdx.x;
    const int wid  = tid >> 5;
    const int lane = tid & 31;

    // ---- B prep (fused): temp transpose in the A region ----
    {
        float* temp = sm;   // 64*66 floats fits in u32[0,8064)
        #pragma unroll 1
        for (int d = 0; d < 2; d++) {
            const int n = n0 + d;
            const int dbase = dn[n] * 64;
            const float* w1n = W1 + (size_t)n * 4096;
            for (int i = tid; i < 4096; i += 256) {
                int e = i >> 6, f = i & 63;
                temp[e * 66 + f] = __ldg(drug_table + dbase + e) * __ldg(w1n + i);
            }
            __syncthreads();
            unsigned* dsth = smu + (d ? B1H : B0H);
            unsigned* dstl = smu + (d ? B1L : B0L);
            for (int j = tid; j < 2048; j += 256) {
                int f = j >> 5, ep = j & 31;
                float v0 = temp[(2 * ep) * 66 + f];
                float v1 = temp[(2 * ep + 1) * 66 + f];
                float h0, l0, h1, l1;
                split2(v0, h0, l0);
                split2(v1, h1, l1);
                dsth[f * 36 + ep] = pack_bf2(h0, h1);
                dstl[f * 36 + ep] = pack_bf2(l0, l1);
            }
            __syncthreads();
        }
    }

    // ---- stage A = split(rela_table), rows 0..99, zero-pad to 112
    {
        const float2* Rf2 = reinterpret_cast<const float2*>(rela_table);
        for (int i = tid; i < 112 * 32; i += 256) {
            int row = i >> 5, ep = i & 31;
            unsigned h = 0u, l = 0u;
            if (row < RLEN) {
                float2 v = __ldg(&Rf2[row * 32 + ep]);
                float h0, l0, h1, l1;
                split2(v.x, h0, l0);
                split2(v.y, h1, l1);
                h = pack_bf2(h0, h1);
                l = pack_bf2(l0, l1);
            }
            smu[A_HI + row * 36 + ep] = h;
            smu[A_LO + row * 36 + ep] = l;
        }
    }
    // ---- w2sum per drug
    #pragma unroll 1
    for (int d = 0; d < 2; d++) {
        int f = tid >> 2, q = tid & 3;
        const float4* p = reinterpret_cast<const float4*>(W2 + (size_t)(n0 + d) * 4096 + f * 64 + q * 16);
        float4 a = p[0], b = p[1], c = p[2], e = p[3];
        psum0[tid] = (a.x + a.y + a.z + a.w) + (b.x + b.y + b.z + b.w)
                   + (c.x + c.y + c.z + c.w) + (e.x + e.y + e.z + e.w);
        __syncthreads();
        if (tid < 64) {
            float* w2 = d ? w2s1 : w2s0;
            w2[tid] = psum0[tid * 4] + psum0[tid * 4 + 1] + psum0[tid * 4 + 2] + psum0[tid * 4 + 3];
        }
        __syncthreads();
    }

    // ---- mma epoch: warp -> (drug = wid>>2, n-quarter q = wid&3)
    const int dsel = wid >> 2;
    const int q    = wid & 3;
    const int g    = lane >> 2;
    const int t    = lane & 3;
    const unsigned* Ah = smu + A_HI;
    const unsigned* Al = smu + A_LO;
    const unsigned* Bh = smu + (dsel ? B1H : B0H);
    const unsigned* Bl = smu + (dsel ? B1L : B0L);

    float D[7][2][4];
    #pragma unroll
    for (int mt = 0; mt < 7; mt++)
        #pragma unroll
        for (int nt = 0; nt < 2; nt++)
            #pragma unroll
            for (int j = 0; j < 4; j++) D[mt][nt][j] = 0.f;

    #pragma unroll
    for (int kp = 0; kp < 32; kp += 8) {
        unsigned bh[2][2], bl[2][2];
        #pragma unroll
        for (int nt = 0; nt < 2; nt++) {
            int fr = q * 16 + nt * 8 + g;
            bh[nt][0] = Bh[fr * 36 + kp + t];
            bh[nt][1] = Bh[fr * 36 + kp + t + 4];
            bl[nt][0] = Bl[fr * 36 + kp + t];
            bl[nt][1] = Bl[fr * 36 + kp + t + 4];
        }
        #pragma unroll
        for (int mt = 0; mt < 7; mt++) {
            int r0 = mt * 16;
            unsigned ah[4], al[4];
            ah[0] = Ah[(r0 + g) * 36 + kp + t];
            ah[1] = Ah[(r0 + g + 8) * 36 + kp + t];
            ah[2] = Ah[(r0 + g) * 36 + kp + t + 4];
            ah[3] = Ah[(r0 + g + 8) * 36 + kp + t + 4];
            al[0] = Al[(r0 + g) * 36 + kp + t];
            al[1] = Al[(r0 + g + 8) * 36 + kp + t];
            al[2] = Al[(r0 + g) * 36 + kp + t + 4];
            al[3] = Al[(r0 + g + 8) * 36 + kp + t + 4];
            #pragma unroll
            for (int nt = 0; nt < 2; nt++) {
                mma16816(D[mt][nt], ah, bh[nt]);
                mma16816(D[mt][nt], ah, bl[nt]);
                mma16816(D[mt][nt], al, bh[nt]);
            }
        }
    }
    __syncthreads();   // staging dead; overlay becomes live

    // ---- write D -> Ms (stride 68 floats), rows < 100
    {
        float* Msd = dsel ? Ms1 : Ms0;
        #pragma unroll
        for (int mt = 0; mt < 7; mt++) {
            int m0 = mt * 16 + g;
            int m1 = m0 + 8;
            #pragma unroll
            for (int nt = 0; nt < 2; nt++) {
                int f = q * 16 + nt * 8 + 2 * t;
                if (m0 < RLEN)
                    *reinterpret_cast<float2*>(Msd + m0 * 68 + f) =
                        make_float2(D[mt][nt][0], D[mt][nt][1]);
                if (m1 < RLEN)
                    *reinterpret_cast<float2*>(Msd + m1 * 68 + f) =
                        make_float2(D[mt][nt][2], D[mt][nt][3]);
            }
        }
    }
    __syncthreads();

    // ---- scores for BOTH drugs, b1 read once
    const int gg  = lane >> 3;
    const int sub = lane & 7;
    const float4 w2a0 = *reinterpret_cast<const float4*>(&w2s0[sub * 8]);
    const float4 w2b0 = *reinterpret_cast<const float4*>(&w2s0[sub * 8 + 4]);
    const float4 w2a1 = *reinterpret_cast<const float4*>(&w2s1[sub * 8]);
    const float4 w2b1 = *reinterpret_cast<const float4*>(&w2s1[sub * 8 + 4]);
    const float4* M0f4 = reinterpret_cast<const float4*>(Ms0);
    const float4* M1f4 = reinterpret_cast<const float4*>(Ms1);
    const float4* b1f4 = reinterpret_cast<const float4*>(b1);
    const int* adjr0 = adjr + (size_t)n0 * SNEI;
    const int* adjr1 = adjr0 + SNEI;
    for (int sbase = wid * 4; sbase < SNEI; sbase += 32) {
        const int s = sbase + gg;
        const int r0i = __ldg(adjr0 + s);
        const int r1i = __ldg(adjr1 + s);
        float4 bv0 = __ldg(&b1f4[s * 16 + sub * 2]);
        float4 bv1 = __ldg(&b1f4[s * 16 + sub * 2 + 1]);
        float4 mA0 = M0f4[r0i * 17 + sub * 2];
        float4 mA1 = M0f4[r0i * 17 + sub * 2 + 1];
        float4 mB0 = M1f4[r1i * 17 + sub * 2];
        float4 mB1 = M1f4[r1i * 17 + sub * 2 + 1];

        float v0, v1;
        v0  = fmaxf(mA0.x + bv0.x, 0.f) * w2a0.x;
        v0  = fmaf(fmaxf(mA0.y + bv0.y, 0.f), w2a0.y, v0);
        v0  = fmaf(fmaxf(mA0.z + bv0.z, 0.f), w2a0.z, v0);
        v0  = fmaf(fmaxf(mA0.w + bv0.w, 0.f), w2a0.w, v0);
        v0  = fmaf(fmaxf(mA1.x + bv1.x, 0.f), w2b0.x, v0);
        v0  = fmaf(fmaxf(mA1.y + bv1.y, 0.f), w2b0.y, v0);
        v0  = fmaf(fmaxf(mA1.z + bv1.z, 0.f), w2b0.z, v0);
        v0  = fmaf(fmaxf(mA1.w + bv1.w, 0.f), w2b0.w, v0);
        v1  = fmaxf(mB0.x + bv0.x, 0.f) * w2a1.x;
        v1  = fmaf(fmaxf(mB0.y + bv0.y, 0.f), w2a1.y, v1);
        v1  = fmaf(fmaxf(mB0.z + bv0.z, 0.f), w2a1.z, v1);
        v1  = fmaf(fmaxf(mB0.w + bv0.w, 0.f), w2a1.w, v1);
        v1  = fmaf(fmaxf(mB1.x + bv1.x, 0.f), w2b1.x, v1);
        v1  = fmaf(fmaxf(mB1.y + bv1.y, 0.f), w2b1.y, v1);
        v1  = fmaf(fmaxf(mB1.z + bv1.z, 0.f), w2b1.z, v1);
        v1  = fmaf(fmaxf(mB1.w + bv1.w, 0.f), w2b1.w, v1);
        v0 += __shfl_xor_sync(0xffffffffu, v0, 4);
        v1 += __shfl_xor_sync(0xffffffffu, v1, 4);
        v0 += __shfl_xor_sync(0xffffffffu, v0, 2);
        v1 += __shfl_xor_sync(0xffffffffu, v1, 2);
        v0 += __shfl_xor_sync(0xffffffffu, v0, 1);
        v1 += __shfl_xor_sync(0xffffffffu, v1, 1);
        if (sub == 0) {
            float bb = g_b2s[s];
            scores0[s] = v0 + bb;
            scores1[s] = v1 + bb;
        }
    }
    __syncthreads();

    // ---- phase 3: HALF-CTA per drug (warps 0-3: d0, warps 4-7: d1)
    {
        const int half  = wid >> 2;
        const int hw    = wid & 3;
        const int htid  = tid & 127;
        const int barid = 1 + half;
        float* scores = half ? scores1 : scores0;
        int*   cidxH  = half ? cidx1  : cidx0;
        int*   cntH   = half ? cnt1   : cnt0;
        float* psumH  = half ? psum2b : psum2a;
        float* redH   = red + half * 16;
        const int n   = n0 + half;

        float lm = -1e30f;
        #pragma unroll
        for (int i = htid; i < SNEI; i += 128) lm = fmaxf(lm, scores[i]);
        #pragma unroll
        for (int o = 16; o; o >>= 1) lm = fmaxf(lm, __shfl_xor_sync(0xffffffffu, lm, o));
        if (lane == 0) redH[hw] = lm;
        asm volatile("bar.sync %0, 128;" :: "r"(barid) : "memory");
        if (htid == 0) {
            redH[8] = fmaxf(fmaxf(redH[0], redH[1]), fmaxf(redH[2], redH[3]));
            *cntH = 0;
        }
        asm volatile("bar.sync %0, 128;" :: "r"(barid) : "memory");
        const float mx = redH[8];

        // exp + sum + fused compact (w > 1e-8 absolute; sum >= 1 so
        // excluded softmax mass <= 1024e-8 = 1e-5)
        float ls = 0.f;
        #pragma unroll
        for (int i = htid; i < SNEI; i += 128) {
            float w = __expf(scores[i] - mx);
            scores[i] = w;
            ls += w;
            if (w > 1e-8f) {
                int p = atomicAdd(cntH, 1);
                cidxH[p] = i;
            }
        }
        #pragma unroll
        for (int o = 16; o; o >>= 1) ls += __shfl_xor_sync(0xffffffffu, ls, o);
        if (lane == 0) redH[4 + hw] = ls;
        asm volatile("bar.sync %0, 128;" :: "r"(barid) : "memory");
        if (htid == 0)
            redH[9] = 1.f / (redH[4] + redH[5] + redH[6] + redH[7]);
        asm volatile("bar.sync %0, 128;" :: "r"(barid) : "memory");
        const float inv = redH[9];
        const int C = *cntH;

        float2 acc = make_float2(0.f, 0.f);
        const float2* entf2 = reinterpret_cast<const float2*>(ent_table);
        const int* adjt_n = adjt + (size_t)n * SNEI;
        for (int j = hw; j < C; j += 4) {
            int s = cidxH[j];
            float w = scores[s] * inv;
            int tt = __ldg(adjt_n + s);
            float2 ev = entf2[(size_t)tt * 32 + lane];
            acc.x = fmaf(w, ev.x, acc.x);
            acc.y = fmaf(w, ev.y, acc.y);
        }
        reinterpret_cast<float2*>(psumH)[hw * 32 + lane] = acc;
        asm volatile("bar.sync %0, 128;" :: "r"(barid) : "memory");
        if (htid < 64) {
            float v = psumH[htid] + psumH[64 + htid] + psumH[128 + htid] + psumH[192 + htid];
            g_we[n * 64 + htid] = v;
        }
    }
}

// ------------------------------------------------------------------
// kernel 2: x = relu([we;de] . lin_W^T + lin_b) + BN partials; the LAST
//   CTA (global counter) performs the BN normalize epilogue and resets
//   the counter (graph-replay safe).
// ------------------------------------------------------------------
__global__ void __launch_bounds__(256)
k_xcomp(const int*   __restrict__ dn,
        const float* __restrict__ drug_table,
        const float* __restrict__ lin_W,
        const float* __restrict__ lin_b,
        const float* __restrict__ gamma,
        const float* __restrict__ beta,
        float* __restrict__ out) {
    __shared__ float lwT[128 * 65];
    __shared__ float vS[4][128];
    __shared__ float s_sum[64], s_sq[64];
    __shared__ int   lastFlag;
    __shared__ float s_scale[64], s_shift[64];

    const int tid = threadIdx.x;
    const int n0  = blockIdx.x * 4;

    #pragma unroll
    for (int i = tid; i < 8192; i += 256) {
        int f = i >> 7, k = i & 127;
        lwT[k * 65 + f] = lin_W[i];
    }
    if (tid < 64) { s_sum[tid] = 0.f; s_sq[tid] = 0.f; }

    #pragma unroll
    for (int i = tid; i < 512; i += 256) {
        int d = i >> 7, k = i & 127;
        int nn = n0 + d;
        float v = 0.f;
        if (nn < NDRUG)
            v = (k < 64) ? g_we[nn * 64 + k]
                         : drug_table[dn[nn] * 64 + (k - 64)];
        vS[d][k] = v;
    }
    __syncthreads();

    const int d = tid >> 6;
    const int f = tid & 63;
    const int nn = n0 + d;

    float acc = 0.f;
    #pragma unroll 8
    for (int k = 0; k < 128; k++)
        acc = fmaf(vS[d][k], lwT[k * 65 + f], acc);
    float x = fmaxf(acc + __ldg(lin_b + f), 0.f);

    if (nn < NDRUG) {
        g_x[nn * 64 + f] = x;
        atomicAdd(&s_sum[f], x);
        atomicAdd(&s_sq[f], x * x);
    }
    __syncthreads();
    if (tid < 64) {
        atomicAdd(&g_sum[tid], s_sum[tid]);
        atomicAdd(&g_sq[tid], s_sq[tid]);
    }

    // ---- last-CTA BN epilogue ----
    __threadfence();
    if (tid == 0) {
        int c = atomicAdd(&g_xdone, 1);
        lastFlag = (c == XCTAS - 1);
    }
    __syncthreads();
    if (lastFlag) {
        __threadfence();   // acquire side of the release/acquire pair
        if (tid < 64) {
            float mean = __ldcg(&g_sum[tid]) * (1.f / NDRUG);
            float var  = __ldcg(&g_sq[tid]) * (1.f / NDRUG) - mean * mean;
            float sc   = rsqrtf(var + 1e-5f) * __ldg(gamma + tid);
            s_scale[tid] = sc;
            s_shift[tid] = __ldg(beta + tid) - mean * sc;
        }
        __syncthreads();
        for (int idx = tid; idx < NDRUG * EDIM; idx += 256)
            out[idx] = __ldcg(&g_x[idx]) * s_scale[idx & 63] + s_shift[idx & 63];
        __syncthreads();
        if (tid == 0) g_xdone = 0;    // reset for next graph replay
    }
}

// ------------------------------------------------------------------
extern "C" void kernel_launch(void* const* d_in, const int* in_sizes, int n_in,
                              void* d_out, int out_size) {
    const int*   dn         = (const int*)  d_in[0];
    const int*   adjt       = (const int*)  d_in[1];
    const int*   adjr       = (const int*)  d_in[2];
    const float* drug_table = (const float*)d_in[3];
    const float* rela_table = (const float*)d_in[4];
    const float* ent_table  = (const float*)d_in[5];
    const float* W1         = (const float*)d_in[6];
    const float* b1         = (const float*)d_in[7];
    const float* W2         = (const float*)d_in[8];
    const float* b2         = (const float*)d_in[9];
    const float* lin_W      = (const float*)d_in[10];
    const float* lin_b      = (const float*)d_in[11];
    const float* gamma      = (const float*)d_in[12];
    const float* beta       = (const float*)d_in[13];
    float* out = (float*)d_out;

    cudaFuncSetAttribute(k_drug, cudaFuncAttributeMaxDynamicSharedMemorySize, K1_SMEM_BYTES);

    k_b2sum<<<SNEI / 8, 256>>>(b2);
    k_drug<<<NPAIR, 256, K1_SMEM_BYTES>>>(dn, adjt, adjr, drug_table, rela_table,
                                          ent_table, W1, b1, W2);
    k_xcomp<<<XCTAS, 256>>>(dn, drug_table, lin_W, lin_b, gamma, beta, out);
}

// round 13
// speedup vs baseline: 1.0194x; 1.0194x over previous
#include <cuda_runtime.h>
#include <cuda_bf16.h>
#include <cstdint>

#define NDRUG 846
#define EDIM  64
#define SNEI  1024
#define RLEN  100
#define NPAIR (NDRUG / 2)    // 423
#define XCTAS ((NDRUG + 3) / 4)   // 212

// ---- scratch (__device__ globals: no allocation allowed) ----
__device__ float g_b2s[SNEI];
__device__ float g_we[NDRUG * EDIM];
__device__ float g_x[NDRUG * EDIM];
__device__ float g_sum[EDIM];
__device__ float g_sq[EDIM];
__device__ int   g_xdone;            // zero-init; self-resetting

__device__ __forceinline__ unsigned pack_bf2(float a, float b) {
    __nv_bfloat16 ha = __float2bfloat16(a), hb = __float2bfloat16(b);
    return (unsigned)__bfloat16_as_ushort(ha) | ((unsigned)__bfloat16_as_ushort(hb) << 16);
}
__device__ __forceinline__ void split2(float x, float& hi, float& lo) {
    __nv_bfloat16 h = __float2bfloat16(x);
    hi = __bfloat162float(h);
    lo = x - hi;
}
__device__ __forceinline__ void mma16816(float* d, const unsigned* a, const unsigned* b) {
    asm volatile(
        "mma.sync.aligned.m16n8k16.row.col.f32.bf16.bf16.f32 "
        "{%0,%1,%2,%3}, {%4,%5,%6,%7}, {%8,%9}, {%0,%1,%2,%3};"
        : "+f"(d[0]), "+f"(d[1]), "+f"(d[2]), "+f"(d[3])
        : "r"(a[0]), "r"(a[1]), "r"(a[2]), "r"(a[3]), "r"(b[0]), "r"(b[1]));
}

// ------------------------------------------------------------------
// kernel 0: b2sum + zero BN accumulators
// ------------------------------------------------------------------
__global__ void k_b2sum(const float* __restrict__ b2) {
    int wid = threadIdx.x >> 5, lane = threadIdx.x & 31;
    if (blockIdx.x == 0 && threadIdx.x < 2 * EDIM) {
        if (threadIdx.x < EDIM) g_sum[threadIdx.x] = 0.f;
        else                    g_sq[threadIdx.x - EDIM] = 0.f;
    }
    int s = blockIdx.x * 8 + wid;
    if (s >= SNEI) return;
    float2 v = *reinterpret_cast<const float2*>(b2 + s * 64 + lane * 2);
    float acc = v.x + v.y;
    #pragma unroll
    for (int o = 16; o; o >>= 1) acc += __shfl_xor_sync(0xffffffffu, acc, o);
    if (lane == 0) g_b2s[s] = acc;
}

// ------------------------------------------------------------------
// kernel 1: one CTA per drug pair.
//
// smem epochs (all within 17664 floats = 70656 B -> 3 CTAs/SM):
//  (a) staging u32: A_hi[0,4032) A_lo[4032,8064) B0h[8064,10368)
//      B0l[10368,12672) B1h[12672,14976) B1l[14976,17280)
//  (b) post-GEMM floats: Ms0@0 (100x68) Ms1@6800  scores0@13600 scores1@14624
//  (c) phase-3 (Ms dead): cidx0@0 cidx1@1024 psum2a@2048 psum2b@2304
//      red@2560 cnt0@2592 cnt1@2593   (scores still live @13600..15648)
//  non-overlay: w2s0@17280 w2s1@17344 psum0@17408..17664
#define K1_SMEM_FLOATS 17664
#define K1_SMEM_BYTES  (K1_SMEM_FLOATS * 4)
#define A_HI 0
#define A_LO 4032
#define B0H  8064
#define B0L  10368
#define B1H  12672
#define B1L  14976

__global__ void __launch_bounds__(256, 3)
k_drug(const int*   __restrict__ dn,
       const int*   __restrict__ adjt,
       const int*   __restrict__ adjr,
       const float* __restrict__ drug_table,
       const float* __restrict__ rela_table,
       const float* __restrict__ ent_table,
       const float* __restrict__ W1,
       const float* __restrict__ b1,
       const float* __restrict__ W2) {
    extern __shared__ float sm[];
    unsigned* smu = reinterpret_cast<unsigned*>(sm);
    // epoch (b)
    float* Ms0     = sm;
    float* Ms1     = sm + 6800;
    float* scores0 = sm + 13600;
    float* scores1 = sm + 14624;
    // epoch (c) — overlays dead Ms region
    int*   cidx0   = (int*)(sm);
    int*   cidx1   = (int*)(sm + 1024);
    float* psum2a  = sm + 2048;
    float* psum2b  = sm + 2304;
    float* red     = sm + 2560;
    int*   cnt0    = (int*)(sm + 2592);
    int*   cnt1    = (int*)(sm + 2593);
    // non-overlay
    float* w2s0  = sm + 17280;
    float* w2s1  = sm + 17344;
    float* psum0 = sm + 17408;

    const int n0   = blockIdx.x * 2;
    const int tid  = threadIdx.x;
    const int wid  = tid >> 5;
    const int lane = tid & 31;

    // ---- B prep (fused): temp transpose in the A region ----
    {
        float* temp = sm;   // 64*66 floats fits in u32[0,8064)
        #pragma unroll 1
        for (int d = 0; d < 2; d++) {
            const int n = n0 + d;
            const int dbase = dn[n] * 64;
            const float* w1n = W1 + (size_t)n * 4096;
            for (int i = tid; i < 4096; i += 256) {
                int e = i >> 6, f = i & 63;
                temp[e * 66 + f] = __ldg(drug_table + dbase + e) * __ldg(w1n + i);
            }
            __syncthreads();
            unsigned* dsth = smu + (d ? B1H : B0H);
            unsigned* dstl = smu + (d ? B1L : B0L);
            for (int j = tid; j < 2048; j += 256) {
                int f = j >> 5, ep = j & 31;
                float v0 = temp[(2 * ep) * 66 + f];
                float v1 = temp[(2 * ep + 1) * 66 + f];
                float h0, l0, h1, l1;
                split2(v0, h0, l0);
                split2(v1, h1, l1);
                dsth[f * 36 + ep] = pack_bf2(h0, h1);
                dstl[f * 36 + ep] = pack_bf2(l0, l1);
            }
            __syncthreads();
        }
    }

    // ---- stage A = split(rela_table), rows 0..99, zero-pad to 112
    {
        const float2* Rf2 = reinterpret_cast<const float2*>(rela_table);
        for (int i = tid; i < 112 * 32; i += 256) {
            int row = i >> 5, ep = i & 31;
            unsigned h = 0u, l = 0u;
            if (row < RLEN) {
                float2 v = __ldg(&Rf2[row * 32 + ep]);
                float h0, l0, h1, l1;
                split2(v.x, h0, l0);
                split2(v.y, h1, l1);
                h = pack_bf2(h0, h1);
                l = pack_bf2(l0, l1);
            }
            smu[A_HI + row * 36 + ep] = h;
            smu[A_LO + row * 36 + ep] = l;
        }
    }
    // ---- w2sum per drug
    #pragma unroll 1
    for (int d = 0; d < 2; d++) {
        int f = tid >> 2, q = tid & 3;
        const float4* p = reinterpret_cast<const float4*>(W2 + (size_t)(n0 + d) * 4096 + f * 64 + q * 16);
        float4 a = p[0], b = p[1], c = p[2], e = p[3];
        psum0[tid] = (a.x + a.y + a.z + a.w) + (b.x + b.y + b.z + b.w)
                   + (c.x + c.y + c.z + c.w) + (e.x + e.y + e.z + e.w);
        __syncthreads();
        if (tid < 64) {
            float* w2 = d ? w2s1 : w2s0;
            w2[tid] = psum0[tid * 4] + psum0[tid * 4 + 1] + psum0[tid * 4 + 2] + psum0[tid * 4 + 3];
        }
        __syncthreads();
    }

    // ---- mma epoch: warp -> (drug = wid>>2, n-quarter q = wid&3)
    const int dsel = wid >> 2;
    const int q    = wid & 3;
    const int g    = lane >> 2;
    const int t    = lane & 3;
    const unsigned* Ah = smu + A_HI;
    const unsigned* Al = smu + A_LO;
    const unsigned* Bh = smu + (dsel ? B1H : B0H);
    const unsigned* Bl = smu + (dsel ? B1L : B0L);

    float D[7][2][4];
    #pragma unroll
    for (int mt = 0; mt < 7; mt++)
        #pragma unroll
        for (int nt = 0; nt < 2; nt++)
            #pragma unroll
            for (int j = 0; j < 4; j++) D[mt][nt][j] = 0.f;

    #pragma unroll
    for (int kp = 0; kp < 32; kp += 8) {
        unsigned bh[2][2], bl[2][2];
        #pragma unroll
        for (int nt = 0; nt < 2; nt++) {
            int fr = q * 16 + nt * 8 + g;
            bh[nt][0] = Bh[fr * 36 + kp + t];
            bh[nt][1] = Bh[fr * 36 + kp + t + 4];
            bl[nt][0] = Bl[fr * 36 + kp + t];
            bl[nt][1] = Bl[fr * 36 + kp + t + 4];
        }
        #pragma unroll
        for (int mt = 0; mt < 7; mt++) {
            int r0 = mt * 16;
            unsigned ah[4], al[4];
            ah[0] = Ah[(r0 + g) * 36 + kp + t];
            ah[1] = Ah[(r0 + g + 8) * 36 + kp + t];
            ah[2] = Ah[(r0 + g) * 36 + kp + t + 4];
            ah[3] = Ah[(r0 + g + 8) * 36 + kp + t + 4];
            al[0] = Al[(r0 + g) * 36 + kp + t];
            al[1] = Al[(r0 + g + 8) * 36 + kp + t];
            al[2] = Al[(r0 + g) * 36 + kp + t + 4];
            al[3] = Al[(r0 + g + 8) * 36 + kp + t + 4];
            #pragma unroll
            for (int nt = 0; nt < 2; nt++) {
                mma16816(D[mt][nt], ah, bh[nt]);
                mma16816(D[mt][nt], ah, bl[nt]);
                mma16816(D[mt][nt], al, bh[nt]);
            }
        }
    }
    __syncthreads();   // staging dead; Ms overlay live

    // ---- write D -> Ms (stride 68 floats), rows < 100
    {
        float* Msd = dsel ? Ms1 : Ms0;
        #pragma unroll
        for (int mt = 0; mt < 7; mt++) {
            int m0 = mt * 16 + g;
            int m1 = m0 + 8;
            #pragma unroll
            for (int nt = 0; nt < 2; nt++) {
                int f = q * 16 + nt * 8 + 2 * t;
                if (m0 < RLEN)
                    *reinterpret_cast<float2*>(Msd + m0 * 68 + f) =
                        make_float2(D[mt][nt][0], D[mt][nt][1]);
                if (m1 < RLEN)
                    *reinterpret_cast<float2*>(Msd + m1 * 68 + f) =
                        make_float2(D[mt][nt][2], D[mt][nt][3]);
            }
        }
    }
    __syncthreads();

    // ---- scores for BOTH drugs, b1 read once
    const int gg  = lane >> 3;
    const int sub = lane & 7;
    const float4 w2a0 = *reinterpret_cast<const float4*>(&w2s0[sub * 8]);
    const float4 w2b0 = *reinterpret_cast<const float4*>(&w2s0[sub * 8 + 4]);
    const float4 w2a1 = *reinterpret_cast<const float4*>(&w2s1[sub * 8]);
    const float4 w2b1 = *reinterpret_cast<const float4*>(&w2s1[sub * 8 + 4]);
    const float4* M0f4 = reinterpret_cast<const float4*>(Ms0);
    const float4* M1f4 = reinterpret_cast<const float4*>(Ms1);
    const float4* b1f4 = reinterpret_cast<const float4*>(b1);
    const int* adjr0 = adjr + (size_t)n0 * SNEI;
    const int* adjr1 = adjr0 + SNEI;
    for (int sbase = wid * 4; sbase < SNEI; sbase += 32) {
        const int s = sbase + gg;
        const int r0i = __ldg(adjr0 + s);
        const int r1i = __ldg(adjr1 + s);
        float4 bv0 = __ldg(&b1f4[s * 16 + sub * 2]);
        float4 bv1 = __ldg(&b1f4[s * 16 + sub * 2 + 1]);
        float4 mA0 = M0f4[r0i * 17 + sub * 2];
        float4 mA1 = M0f4[r0i * 17 + sub * 2 + 1];
        float4 mB0 = M1f4[r1i * 17 + sub * 2];
        float4 mB1 = M1f4[r1i * 17 + sub * 2 + 1];

        float v0, v1;
        v0  = fmaxf(mA0.x + bv0.x, 0.f) * w2a0.x;
        v0  = fmaf(fmaxf(mA0.y + bv0.y, 0.f), w2a0.y, v0);
        v0  = fmaf(fmaxf(mA0.z + bv0.z, 0.f), w2a0.z, v0);
        v0  = fmaf(fmaxf(mA0.w + bv0.w, 0.f), w2a0.w, v0);
        v0  = fmaf(fmaxf(mA1.x + bv1.x, 0.f), w2b0.x, v0);
        v0  = fmaf(fmaxf(mA1.y + bv1.y, 0.f), w2b0.y, v0);
        v0  = fmaf(fmaxf(mA1.z + bv1.z, 0.f), w2b0.z, v0);
        v0  = fmaf(fmaxf(mA1.w + bv1.w, 0.f), w2b0.w, v0);
        v1  = fmaxf(mB0.x + bv0.x, 0.f) * w2a1.x;
        v1  = fmaf(fmaxf(mB0.y + bv0.y, 0.f), w2a1.y, v1);
        v1  = fmaf(fmaxf(mB0.z + bv0.z, 0.f), w2a1.z, v1);
        v1  = fmaf(fmaxf(mB0.w + bv0.w, 0.f), w2a1.w, v1);
        v1  = fmaf(fmaxf(mB1.x + bv1.x, 0.f), w2b1.x, v1);
        v1  = fmaf(fmaxf(mB1.y + bv1.y, 0.f), w2b1.y, v1);
        v1  = fmaf(fmaxf(mB1.z + bv1.z, 0.f), w2b1.z, v1);
        v1  = fmaf(fmaxf(mB1.w + bv1.w, 0.f), w2b1.w, v1);
        v0 += __shfl_xor_sync(0xffffffffu, v0, 4);
        v1 += __shfl_xor_sync(0xffffffffu, v1, 4);
        v0 += __shfl_xor_sync(0xffffffffu, v0, 2);
        v1 += __shfl_xor_sync(0xffffffffu, v1, 2);
        v0 += __shfl_xor_sync(0xffffffffu, v0, 1);
        v1 += __shfl_xor_sync(0xffffffffu, v1, 1);
        if (sub == 0) {
            float bb = g_b2s[s];
            scores0[s] = v0 + bb;
            scores1[s] = v1 + bb;
        }
    }
    __syncthreads();   // last Ms read done -> phase-3 overlay may write

    // ---- phase 3: HALF-CTA per drug (warps 0-3: d0, warps 4-7: d1)
    {
        const int half  = wid >> 2;
        const int hw    = wid & 3;
        const int htid  = tid & 127;
        const int barid = 1 + half;
        float* scores = half ? scores1 : scores0;
        int*   cidxH  = half ? cidx1  : cidx0;
        int*   cntH   = half ? cnt1   : cnt0;
        float* psumH  = half ? psum2b : psum2a;
        float* redH   = red + half * 16;
        const int n   = n0 + half;

        float lm = -1e30f;
        #pragma unroll
        for (int i = htid; i < SNEI; i += 128) lm = fmaxf(lm, scores[i]);
        #pragma unroll
        for (int o = 16; o; o >>= 1) lm = fmaxf(lm, __shfl_xor_sync(0xffffffffu, lm, o));
        if (lane == 0) redH[hw] = lm;
        asm volatile("bar.sync %0, 128;" :: "r"(barid) : "memory");
        if (htid == 0) {
            redH[8] = fmaxf(fmaxf(redH[0], redH[1]), fmaxf(redH[2], redH[3]));
            *cntH = 0;
        }
        asm volatile("bar.sync %0, 128;" :: "r"(barid) : "memory");
        const float mx = redH[8];

        // exp + sum + fused compact (w > 1e-8 absolute; sum >= 1 so
        // excluded softmax mass <= 1e-5)
        float ls = 0.f;
        #pragma unroll
        for (int i = htid; i < SNEI; i += 128) {
            float w = __expf(scores[i] - mx);
            scores[i] = w;
            ls += w;
            if (w > 1e-8f) {
                int p = atomicAdd(cntH, 1);
                cidxH[p] = i;
            }
        }
        #pragma unroll
        for (int o = 16; o; o >>= 1) ls += __shfl_xor_sync(0xffffffffu, ls, o);
        if (lane == 0) redH[4 + hw] = ls;
        asm volatile("bar.sync %0, 128;" :: "r"(barid) : "memory");
        if (htid == 0)
            redH[9] = 1.f / (redH[4] + redH[5] + redH[6] + redH[7]);
        asm volatile("bar.sync %0, 128;" :: "r"(barid) : "memory");
        const float inv = redH[9];
        const int C = *cntH;

        float2 acc = make_float2(0.f, 0.f);
        const float2* entf2 = reinterpret_cast<const float2*>(ent_table);
        const int* adjt_n = adjt + (size_t)n * SNEI;
        for (int j = hw; j < C; j += 4) {
            int s = cidxH[j];
            float w = scores[s] * inv;
            int tt = __ldg(adjt_n + s);
            float2 ev = entf2[(size_t)tt * 32 + lane];
            acc.x = fmaf(w, ev.x, acc.x);
            acc.y = fmaf(w, ev.y, acc.y);
        }
        reinterpret_cast<float2*>(psumH)[hw * 32 + lane] = acc;
        asm volatile("bar.sync %0, 128;" :: "r"(barid) : "memory");
        if (htid < 64) {
            float v = psumH[htid] + psumH[64 + htid] + psumH[128 + htid] + psumH[192 + htid];
            g_we[n * 64 + htid] = v;
        }
    }
}

// ------------------------------------------------------------------
// kernel 2: x = relu([we;de] . lin_W^T + lin_b) + BN partials; the LAST
//   CTA performs the BN normalize epilogue and resets the counter.
// ------------------------------------------------------------------
__global__ void __launch_bounds__(256)
k_xcomp(const int*   __restrict__ dn,
        const float* __restrict__ drug_table,
        const float* __restrict__ lin_W,
        const float* __restrict__ lin_b,
        const float* __restrict__ gamma,
        const float* __restrict__ beta,
        float* __restrict__ out) {
    __shared__ float lwT[128 * 65];
    __shared__ float vS[4][128];
    __shared__ float s_sum[64], s_sq[64];
    __shared__ int   lastFlag;
    __shared__ float s_scale[64], s_shift[64];

    const int tid = threadIdx.x;
    const int n0  = blockIdx.x * 4;

    #pragma unroll
    for (int i = tid; i < 8192; i += 256) {
        int f = i >> 7, k = i & 127;
        lwT[k * 65 + f] = lin_W[i];
    }
    if (tid < 64) { s_sum[tid] = 0.f; s_sq[tid] = 0.f; }

    #pragma unroll
    for (int i = tid; i < 512; i += 256) {
        int d = i >> 7, k = i & 127;
        int nn = n0 + d;
        float v = 0.f;
        if (nn < NDRUG)
            v = (k < 64) ? g_we[nn * 64 + k]
                         : drug_table[dn[nn] * 64 + (k - 64)];
        vS[d][k] = v;
    }
    __syncthreads();

    const int d = tid >> 6;
    const int f = tid & 63;
    const int nn = n0 + d;

    float acc = 0.f;
    #pragma unroll 8
    for (int k = 0; k < 128; k++)
        acc = fmaf(vS[d][k], lwT[k * 65 + f], acc);
    float x = fmaxf(acc + __ldg(lin_b + f), 0.f);

    if (nn < NDRUG) {
        g_x[nn * 64 + f] = x;
        atomicAdd(&s_sum[f], x);
        atomicAdd(&s_sq[f], x * x);
    }
    __syncthreads();
    if (tid < 64) {
        atomicAdd(&g_sum[tid], s_sum[tid]);
        atomicAdd(&g_sq[tid], s_sq[tid]);
    }

    // ---- last-CTA BN epilogue ----
    __threadfence();
    if (tid == 0) {
        int c = atomicAdd(&g_xdone, 1);
        lastFlag = (c == XCTAS - 1);
    }
    __syncthreads();
    if (lastFlag) {
        __threadfence();
        if (tid < 64) {
            float mean = __ldcg(&g_sum[tid]) * (1.f / NDRUG);
            float var  = __ldcg(&g_sq[tid]) * (1.f / NDRUG) - mean * mean;
            float sc   = rsqrtf(var + 1e-5f) * __ldg(gamma + tid);
            s_scale[tid] = sc;
            s_shift[tid] = __ldg(beta + tid) - mean * sc;
        }
        __syncthreads();
        for (int idx = tid; idx < NDRUG * EDIM; idx += 256)
            out[idx] = __ldcg(&g_x[idx]) * s_scale[idx & 63] + s_shift[idx & 63];
        __syncthreads();
        if (tid == 0) g_xdone = 0;    // reset for next graph replay
    }
}

// ------------------------------------------------------------------
extern "C" void kernel_launch(void* const* d_in, const int* in_sizes, int n_in,
                              void* d_out, int out_size) {
    const int*   dn         = (const int*)  d_in[0];
    const int*   adjt       = (const int*)  d_in[1];
    const int*   adjr       = (const int*)  d_in[2];
    const float* drug_table = (const float*)d_in[3];
    const float* rela_table = (const float*)d_in[4];
    const float* ent_table  = (const float*)d_in[5];
    const float* W1         = (const float*)d_in[6];
    const float* b1         = (const float*)d_in[7];
    const float* W2         = (const float*)d_in[8];
    const float* b2         = (const float*)d_in[9];
    const float* lin_W      = (const float*)d_in[10];
    const float* lin_b      = (const float*)d_in[11];
    const float* gamma      = (const float*)d_in[12];
    const float* beta       = (const float*)d_in[13];
    float* out = (float*)d_out;

    cudaFuncSetAttribute(k_drug, cudaFuncAttributeMaxDynamicSharedMemorySize, K1_SMEM_BYTES);

    k_b2sum<<<SNEI / 8, 256>>>(b2);
    k_drug<<<NPAIR, 256, K1_SMEM_BYTES>>>(dn, adjt, adjr, drug_table, rela_table,
                                          ent_table, W1, b1, W2);
    k_xcomp<<<XCTAS, 256>>>(dn, drug_table, lin_W, lin_b, gamma, beta, out);
}

// round 14
// speedup vs baseline: 1.8045x; 1.7701x over previous
#include <cuda_runtime.h>
#include <cuda_bf16.h>
#include <cstdint>

#define NDRUG 846
#define EDIM  64
#define SNEI  1024
#define RLEN  100
#define NPAIR (NDRUG / 2)    // 423
#define XCTAS ((NDRUG + 3) / 4)   // 212

// ---- scratch (__device__ globals: no allocation allowed) ----
__device__ float g_b2s[SNEI];
__device__ float g_we[NDRUG * EDIM];
__device__ float g_x[NDRUG * EDIM];
__device__ float g_sum[EDIM];
__device__ float g_sq[EDIM];

__device__ __forceinline__ unsigned pack_bf2(float a, float b) {
    __nv_bfloat16 ha = __float2bfloat16(a), hb = __float2bfloat16(b);
    return (unsigned)__bfloat16_as_ushort(ha) | ((unsigned)__bfloat16_as_ushort(hb) << 16);
}
__device__ __forceinline__ void split2(float x, float& hi, float& lo) {
    __nv_bfloat16 h = __float2bfloat16(x);
    hi = __bfloat162float(h);
    lo = x - hi;
}
__device__ __forceinline__ void mma16816(float* d, const unsigned* a, const unsigned* b) {
    asm volatile(
        "mma.sync.aligned.m16n8k16.row.col.f32.bf16.bf16.f32 "
        "{%0,%1,%2,%3}, {%4,%5,%6,%7}, {%8,%9}, {%0,%1,%2,%3};"
        : "+f"(d[0]), "+f"(d[1]), "+f"(d[2]), "+f"(d[3])
        : "r"(a[0]), "r"(a[1]), "r"(a[2]), "r"(a[3]), "r"(b[0]), "r"(b[1]));
}

// ------------------------------------------------------------------
// kernel 0: b2sum + zero BN accumulators
// ------------------------------------------------------------------
__global__ void k_b2sum(const float* __restrict__ b2) {
    int wid = threadIdx.x >> 5, lane = threadIdx.x & 31;
    if (blockIdx.x == 0 && threadIdx.x < 2 * EDIM) {
        if (threadIdx.x < EDIM) g_sum[threadIdx.x] = 0.f;
        else                    g_sq[threadIdx.x - EDIM] = 0.f;
    }
    int s = blockIdx.x * 8 + wid;
    if (s >= SNEI) return;
    float2 v = *reinterpret_cast<const float2*>(b2 + s * 64 + lane * 2);
    float acc = v.x + v.y;
    #pragma unroll
    for (int o = 16; o; o >>= 1) acc += __shfl_xor_sync(0xffffffffu, acc, o);
    if (lane == 0) g_b2s[s] = acc;
}

// ------------------------------------------------------------------
// kernel 1: one CTA per drug pair.
//
// smem epochs (17664 floats = 70656 B -> 3 CTAs/SM, single wave):
//  (a) staging u32: A_hi[0,4032) A_lo[4032,8064) B0h[8064,10368)
//      B0l[10368,12672) B1h[12672,14976) B1l[14976,17280)
//  (b) post-GEMM floats: Ms0@0 (100x68) Ms1@6800  scores0@13600 scores1@14624
//  (c) phase-3 (Ms dead): cidx0@0 cidx1@1024 psum2a@2048 psum2b@2304
//      red@2560 cnt0@2592 cnt1@2593
//  non-overlay: w2s0@17280 w2s1@17344 psum0@17408..17664
#define K1_SMEM_FLOATS 17664
#define K1_SMEM_BYTES  (K1_SMEM_FLOATS * 4)
#define A_HI 0
#define A_LO 4032
#define B0H  8064
#define B0L  10368
#define B1H  12672
#define B1L  14976

__global__ void __launch_bounds__(256, 3)
k_drug(const int*   __restrict__ dn,
       const int*   __restrict__ adjt,
       const int*   __restrict__ adjr,
       const float* __restrict__ drug_table,
       const float* __restrict__ rela_table,
       const float* __restrict__ ent_table,
       const float* __restrict__ W1,
       const float* __restrict__ b1,
       const float* __restrict__ W2) {
    extern __shared__ float sm[];
    unsigned* smu = reinterpret_cast<unsigned*>(sm);
    // epoch (b)
    float* Ms0     = sm;
    float* Ms1     = sm + 6800;
    float* scores0 = sm + 13600;
    float* scores1 = sm + 14624;
    // epoch (c) — overlays dead Ms region
    int*   cidx0   = (int*)(sm);
    int*   cidx1   = (int*)(sm + 1024);
    float* psum2a  = sm + 2048;
    float* psum2b  = sm + 2304;
    float* red     = sm + 2560;
    int*   cnt0    = (int*)(sm + 2592);
    int*   cnt1    = (int*)(sm + 2593);
    // non-overlay
    float* w2s0  = sm + 17280;
    float* w2s1  = sm + 17344;
    float* psum0 = sm + 17408;

    const int n0   = blockIdx.x * 2;
    const int tid  = threadIdx.x;
    const int wid  = tid >> 5;
    const int lane = tid & 31;

    // ---- B prep (fused): temp transpose in the A region ----
    {
        float* temp = sm;   // 64*66 floats fits in u32[0,8064)
        #pragma unroll 1
        for (int d = 0; d < 2; d++) {
            const int n = n0 + d;
            const int dbase = dn[n] * 64;
            const float* w1n = W1 + (size_t)n * 4096;
            for (int i = tid; i < 4096; i += 256) {
                int e = i >> 6, f = i & 63;
                temp[e * 66 + f] = __ldg(drug_table + dbase + e) * __ldg(w1n + i);
            }
            __syncthreads();
            unsigned* dsth = smu + (d ? B1H : B0H);
            unsigned* dstl = smu + (d ? B1L : B0L);
            for (int j = tid; j < 2048; j += 256) {
                int f = j >> 5, ep = j & 31;
                float v0 = temp[(2 * ep) * 66 + f];
                float v1 = temp[(2 * ep + 1) * 66 + f];
                float h0, l0, h1, l1;
                split2(v0, h0, l0);
                split2(v1, h1, l1);
                dsth[f * 36 + ep] = pack_bf2(h0, h1);
                dstl[f * 36 + ep] = pack_bf2(l0, l1);
            }
            __syncthreads();
        }
    }

    // ---- stage A = split(rela_table), rows 0..99, zero-pad to 112
    {
        const float2* Rf2 = reinterpret_cast<const float2*>(rela_table);
        for (int i = tid; i < 112 * 32; i += 256) {
            int row = i >> 5, ep = i & 31;
            unsigned h = 0u, l = 0u;
            if (row < RLEN) {
                float2 v = __ldg(&Rf2[row * 32 + ep]);
                float h0, l0, h1, l1;
                split2(v.x, h0, l0);
                split2(v.y, h1, l1);
                h = pack_bf2(h0, h1);
                l = pack_bf2(l0, l1);
            }
            smu[A_HI + row * 36 + ep] = h;
            smu[A_LO + row * 36 + ep] = l;
        }
    }
    // ---- w2sum per drug
    #pragma unroll 1
    for (int d = 0; d < 2; d++) {
        int f = tid >> 2, q = tid & 3;
        const float4* p = reinterpret_cast<const float4*>(W2 + (size_t)(n0 + d) * 4096 + f * 64 + q * 16);
        float4 a = p[0], b = p[1], c = p[2], e = p[3];
        psum0[tid] = (a.x + a.y + a.z + a.w) + (b.x + b.y + b.z + b.w)
                   + (c.x + c.y + c.z + c.w) + (e.x + e.y + e.z + e.w);
        __syncthreads();
        if (tid < 64) {
            float* w2 = d ? w2s1 : w2s0;
            w2[tid] = psum0[tid * 4] + psum0[tid * 4 + 1] + psum0[tid * 4 + 2] + psum0[tid * 4 + 3];
        }
        __syncthreads();
    }

    // ---- mma epoch: warp -> (drug = wid>>2, n-quarter q = wid&3)
    const int dsel = wid >> 2;
    const int q    = wid & 3;
    const int g    = lane >> 2;
    const int t    = lane & 3;
    const unsigned* Ah = smu + A_HI;
    const unsigned* Al = smu + A_LO;
    const unsigned* Bh = smu + (dsel ? B1H : B0H);
    const unsigned* Bl = smu + (dsel ? B1L : B0L);

    float D[7][2][4];
    #pragma unroll
    for (int mt = 0; mt < 7; mt++)
        #pragma unroll
        for (int nt = 0; nt < 2; nt++)
            #pragma unroll
            for (int j = 0; j < 4; j++) D[mt][nt][j] = 0.f;

    #pragma unroll
    for (int kp = 0; kp < 32; kp += 8) {
        unsigned bh[2][2], bl[2][2];
        #pragma unroll
        for (int nt = 0; nt < 2; nt++) {
            int fr = q * 16 + nt * 8 + g;
            bh[nt][0] = Bh[fr * 36 + kp + t];
            bh[nt][1] = Bh[fr * 36 + kp + t + 4];
            bl[nt][0] = Bl[fr * 36 + kp + t];
            bl[nt][1] = Bl[fr * 36 + kp + t + 4];
        }
        #pragma unroll
        for (int mt = 0; mt < 7; mt++) {
            int r0 = mt * 16;
            unsigned ah[4], al[4];
            ah[0] = Ah[(r0 + g) * 36 + kp + t];
            ah[1] = Ah[(r0 + g + 8) * 36 + kp + t];
            ah[2] = Ah[(r0 + g) * 36 + kp + t + 4];
            ah[3] = Ah[(r0 + g + 8) * 36 + kp + t + 4];
            al[0] = Al[(r0 + g) * 36 + kp + t];
            al[1] = Al[(r0 + g + 8) * 36 + kp + t];
            al[2] = Al[(r0 + g) * 36 + kp + t + 4];
            al[3] = Al[(r0 + g + 8) * 36 + kp + t + 4];
            #pragma unroll
            for (int nt = 0; nt < 2; nt++) {
                mma16816(D[mt][nt], ah, bh[nt]);
                mma16816(D[mt][nt], ah, bl[nt]);
                mma16816(D[mt][nt], al, bh[nt]);
            }
        }
    }
    __syncthreads();   // staging dead; Ms overlay live

    // ---- write D -> Ms (stride 68 floats), rows < 100
    {
        float* Msd = dsel ? Ms1 : Ms0;
        #pragma unroll
        for (int mt = 0; mt < 7; mt++) {
            int m0 = mt * 16 + g;
            int m1 = m0 + 8;
            #pragma unroll
            for (int nt = 0; nt < 2; nt++) {
                int f = q * 16 + nt * 8 + 2 * t;
                if (m0 < RLEN)
                    *reinterpret_cast<float2*>(Msd + m0 * 68 + f) =
                        make_float2(D[mt][nt][0], D[mt][nt][1]);
                if (m1 < RLEN)
                    *reinterpret_cast<float2*>(Msd + m1 * 68 + f) =
                        make_float2(D[mt][nt][2], D[mt][nt][3]);
            }
        }
    }
    __syncthreads();

    // ---- scores for BOTH drugs, b1 read once
    const int gg  = lane >> 3;
    const int sub = lane & 7;
    const float4 w2a0 = *reinterpret_cast<const float4*>(&w2s0[sub * 8]);
    const float4 w2b0 = *reinterpret_cast<const float4*>(&w2s0[sub * 8 + 4]);
    const float4 w2a1 = *reinterpret_cast<const float4*>(&w2s1[sub * 8]);
    const float4 w2b1 = *reinterpret_cast<const float4*>(&w2s1[sub * 8 + 4]);
    const float4* M0f4 = reinterpret_cast<const float4*>(Ms0);
    const float4* M1f4 = reinterpret_cast<const float4*>(Ms1);
    const float4* b1f4 = reinterpret_cast<const float4*>(b1);
    const int* adjr0 = adjr + (size_t)n0 * SNEI;
    const int* adjr1 = adjr0 + SNEI;
    for (int sbase = wid * 4; sbase < SNEI; sbase += 32) {
        const int s = sbase + gg;
        const int r0i = __ldg(adjr0 + s);
        const int r1i = __ldg(adjr1 + s);
        float4 bv0 = __ldg(&b1f4[s * 16 + sub * 2]);
        float4 bv1 = __ldg(&b1f4[s * 16 + sub * 2 + 1]);
        float4 mA0 = M0f4[r0i * 17 + sub * 2];
        float4 mA1 = M0f4[r0i * 17 + sub * 2 + 1];
        float4 mB0 = M1f4[r1i * 17 + sub * 2];
        float4 mB1 = M1f4[r1i * 17 + sub * 2 + 1];

        float v0, v1;
        v0  = fmaxf(mA0.x + bv0.x, 0.f) * w2a0.x;
        v0  = fmaf(fmaxf(mA0.y + bv0.y, 0.f), w2a0.y, v0);
        v0  = fmaf(fmaxf(mA0.z + bv0.z, 0.f), w2a0.z, v0);
        v0  = fmaf(fmaxf(mA0.w + bv0.w, 0.f), w2a0.w, v0);
        v0  = fmaf(fmaxf(mA1.x + bv1.x, 0.f), w2b0.x, v0);
        v0  = fmaf(fmaxf(mA1.y + bv1.y, 0.f), w2b0.y, v0);
        v0  = fmaf(fmaxf(mA1.z + bv1.z, 0.f), w2b0.z, v0);
        v0  = fmaf(fmaxf(mA1.w + bv1.w, 0.f), w2b0.w, v0);
        v1  = fmaxf(mB0.x + bv0.x, 0.f) * w2a1.x;
        v1  = fmaf(fmaxf(mB0.y + bv0.y, 0.f), w2a1.y, v1);
        v1  = fmaf(fmaxf(mB0.z + bv0.z, 0.f), w2a1.z, v1);
        v1  = fmaf(fmaxf(mB0.w + bv0.w, 0.f), w2a1.w, v1);
        v1  = fmaf(fmaxf(mB1.x + bv1.x, 0.f), w2b1.x, v1);
        v1  = fmaf(fmaxf(mB1.y + bv1.y, 0.f), w2b1.y, v1);
        v1  = fmaf(fmaxf(mB1.z + bv1.z, 0.f), w2b1.z, v1);
        v1  = fmaf(fmaxf(mB1.w + bv1.w, 0.f), w2b1.w, v1);
        v0 += __shfl_xor_sync(0xffffffffu, v0, 4);
        v1 += __shfl_xor_sync(0xffffffffu, v1, 4);
        v0 += __shfl_xor_sync(0xffffffffu, v0, 2);
        v1 += __shfl_xor_sync(0xffffffffu, v1, 2);
        v0 += __shfl_xor_sync(0xffffffffu, v0, 1);
        v1 += __shfl_xor_sync(0xffffffffu, v1, 1);
        if (sub == 0) {
            float bb = g_b2s[s];
            scores0[s] = v0 + bb;
            scores1[s] = v1 + bb;
        }
    }
    __syncthreads();   // last Ms read done -> phase-3 overlay may write

    // ---- phase 3: HALF-CTA per drug (warps 0-3: d0, warps 4-7: d1)
    {
        const int half  = wid >> 2;
        const int hw    = wid & 3;
        const int htid  = tid & 127;
        const int barid = 1 + half;
        float* scores = half ? scores1 : scores0;
        int*   cidxH  = half ? cidx1  : cidx0;
        int*   cntH   = half ? cnt1   : cnt0;
        float* psumH  = half ? psum2b : psum2a;
        float* redH   = red + half * 16;
        const int n   = n0 + half;

        float lm = -1e30f;
        #pragma unroll
        for (int i = htid; i < SNEI; i += 128) lm = fmaxf(lm, scores[i]);
        #pragma unroll
        for (int o = 16; o; o >>= 1) lm = fmaxf(lm, __shfl_xor_sync(0xffffffffu, lm, o));
        if (lane == 0) redH[hw] = lm;
        asm volatile("bar.sync %0, 128;" :: "r"(barid) : "memory");
        if (htid == 0) {
            redH[8] = fmaxf(fmaxf(redH[0], redH[1]), fmaxf(redH[2], redH[3]));
            *cntH = 0;
        }
        asm volatile("bar.sync %0, 128;" :: "r"(barid) : "memory");
        const float mx = redH[8];

        // exp + sum + fused compact (w > 1e-8 absolute; sum >= 1 so
        // excluded softmax mass <= 1e-5)
        float ls = 0.f;
        #pragma unroll
        for (int i = htid; i < SNEI; i += 128) {
            float w = __expf(scores[i] - mx);
            scores[i] = w;
            ls += w;
            if (w > 1e-8f) {
                int p = atomicAdd(cntH, 1);
                cidxH[p] = i;
            }
        }
        #pragma unroll
        for (int o = 16; o; o >>= 1) ls += __shfl_xor_sync(0xffffffffu, ls, o);
        if (lane == 0) redH[4 + hw] = ls;
        asm volatile("bar.sync %0, 128;" :: "r"(barid) : "memory");
        if (htid == 0)
            redH[9] = 1.f / (redH[4] + redH[5] + redH[6] + redH[7]);
        asm volatile("bar.sync %0, 128;" :: "r"(barid) : "memory");
        const float inv = redH[9];
        const int C = *cntH;

        float2 acc = make_float2(0.f, 0.f);
        const float2* entf2 = reinterpret_cast<const float2*>(ent_table);
        const int* adjt_n = adjt + (size_t)n * SNEI;
        for (int j = hw; j < C; j += 4) {
            int s = cidxH[j];
            float w = scores[s] * inv;
            int tt = __ldg(adjt_n + s);
            float2 ev = entf2[(size_t)tt * 32 + lane];
            acc.x = fmaf(w, ev.x, acc.x);
            acc.y = fmaf(w, ev.y, acc.y);
        }
        reinterpret_cast<float2*>(psumH)[hw * 32 + lane] = acc;
        asm volatile("bar.sync %0, 128;" :: "r"(barid) : "memory");
        if (htid < 64) {
            float v = psumH[htid] + psumH[64 + htid] + psumH[128 + htid] + psumH[192 + htid];
            g_we[n * 64 + htid] = v;
        }
    }
}

// ------------------------------------------------------------------
// kernel 2a: x = relu([we;de] . lin_W^T + lin_b) + BN partials
// ------------------------------------------------------------------
__global__ void __launch_bounds__(256)
k_xcomp(const int*   __restrict__ dn,
        const float* __restrict__ drug_table,
        const float* __restrict__ lin_W,
        const float* __restrict__ lin_b) {
    __shared__ float lwT[128 * 65];
    __shared__ float vS[4][128];
    __shared__ float s_sum[64], s_sq[64];

    const int tid = threadIdx.x;
    const int n0  = blockIdx.x * 4;

    #pragma unroll
    for (int i = tid; i < 8192; i += 256) {
        int f = i >> 7, k = i & 127;
        lwT[k * 65 + f] = lin_W[i];
    }
    if (tid < 64) { s_sum[tid] = 0.f; s_sq[tid] = 0.f; }

    #pragma unroll
    for (int i = tid; i < 512; i += 256) {
        int d = i >> 7, k = i & 127;
        int nn = n0 + d;
        float v = 0.f;
        if (nn < NDRUG)
            v = (k < 64) ? g_we[nn * 64 + k]
                         : drug_table[dn[nn] * 64 + (k - 64)];
        vS[d][k] = v;
    }
    __syncthreads();

    const int d = tid >> 6;
    const int f = tid & 63;
    const int nn = n0 + d;

    float acc = 0.f;
    #pragma unroll 8
    for (int k = 0; k < 128; k++)
        acc = fmaf(vS[d][k], lwT[k * 65 + f], acc);
    float x = fmaxf(acc + __ldg(lin_b + f), 0.f);

    if (nn < NDRUG) {
        g_x[nn * 64 + f] = x;
        atomicAdd(&s_sum[f], x);
        atomicAdd(&s_sq[f], x * x);
    }
    __syncthreads();
    if (tid < 64) {
        atomicAdd(&g_sum[tid], s_sum[tid]);
        atomicAdd(&g_sq[tid], s_sq[tid]);
    }
}

// ------------------------------------------------------------------
// kernel 2b: BN normalize (parallel, 212 CTAs)
// ------------------------------------------------------------------
__global__ void __launch_bounds__(256)
k_bnorm(const float* __restrict__ gamma,
        const float* __restrict__ beta,
        float* __restrict__ out) {
    int idx = blockIdx.x * 256 + threadIdx.x;
    if (idx >= NDRUG * EDIM) return;
    int f = idx & 63;
    float mean = g_sum[f] * (1.f / NDRUG);
    float var  = g_sq[f] * (1.f / NDRUG) - mean * mean;
    float scal = rsqrtf(var + 1e-5f) * __ldg(gamma + f);
    out[idx] = (g_x[idx] - mean) * scal + __ldg(beta + f);
}

// ------------------------------------------------------------------
extern "C" void kernel_launch(void* const* d_in, const int* in_sizes, int n_in,
                              void* d_out, int out_size) {
    const int*   dn         = (const int*)  d_in[0];
    const int*   adjt       = (const int*)  d_in[1];
    const int*   adjr       = (const int*)  d_in[2];
    const float* drug_table = (const float*)d_in[3];
    const float* rela_table = (const float*)d_in[4];
    const float* ent_table  = (const float*)d_in[5];
    const float* W1         = (const float*)d_in[6];
    const float* b1         = (const float*)d_in[7];
    const float* W2         = (const float*)d_in[8];
    const float* b2         = (const float*)d_in[9];
    const float* lin_W      = (const float*)d_in[10];
    const float* lin_b      = (const float*)d_in[11];
    const float* gamma      = (const float*)d_in[12];
    const float* beta       = (const float*)d_in[13];
    float* out = (float*)d_out;

    cudaFuncSetAttribute(k_drug, cudaFuncAttributeMaxDynamicSharedMemorySize, K1_SMEM_BYTES);

    k_b2sum<<<SNEI / 8, 256>>>(b2);
    k_drug<<<NPAIR, 256, K1_SMEM_BYTES>>>(dn, adjt, adjr, drug_table, rela_table,
                                          ent_table, W1, b1, W2);
    k_xcomp<<<XCTAS, 256>>>(dn, drug_table, lin_W, lin_b);
    k_bnorm<<<(NDRUG * EDIM + 255) / 256, 256>>>(gamma, beta, out);
}